// round 4
// baseline (speedup 1.0000x reference)
#include <cuda_runtime.h>
#include <cuda_fp16.h>
#include <cuda_bf16.h>

#define SEQ   2048
#define DIN   1024
#define DHID  2048
#define DOUT  512
#define NPROJ 8192   // 4 gates * DHID

// ---- recurrent kernel geometry ----
#define NJ       14             // hidden units per CTA (2 per warp)
#define RWARPS   7
#define RTHREADS (RWARPS * 32)  // 224
#define RGRID    147            // ceil(2048/14) compute CTAs, all co-resident
#define SMEM_REC (NJ * 4 * DHID * 2)  // 229376 B of bf16 weights

#define SENT 1e30f              // sentinel: |valid h| < 1 always (tanh*sigmoid)

// ---- device scratch (allocation-free requirement) ----
__device__ float          g_xproj[(size_t)SEQ * NPROJ];   // 64 MB: [t][g*2048+j]
__device__ __nv_bfloat16  g_wh[(size_t)4 * DHID * DHID];  // 32 MB: [(g*2048+j)*2048+k]
__device__ float          g_h[4][DHID];                   // 4-slot rotating h buffers

struct Ptrs { const float* W[4]; const float* b[4]; };

// ---- strong memory ops: data-driven sync primitives ----
__device__ __forceinline__ float4 ld_vol4(const float* p) {
    float4 v;
    asm volatile("ld.volatile.global.v4.f32 {%0,%1,%2,%3}, [%4];"
                 : "=f"(v.x), "=f"(v.y), "=f"(v.z), "=f"(v.w) : "l"(p) : "memory");
    return v;
}
__device__ __forceinline__ void st_rlx(float* p, float v) {
    asm volatile("st.relaxed.gpu.global.f32 [%0], %1;" :: "l"(p), "f"(v) : "memory");
}
__device__ __forceinline__ void st_rel(float* p, float v) {
    asm volatile("st.release.gpu.global.f32 [%0], %1;" :: "l"(p), "f"(v) : "memory");
}

// ---------------------------------------------------------------------------
// init: buf0 = h[0] = 0, buf1..3 = sentinel (graph-replay safe: runs per launch)
// ---------------------------------------------------------------------------
__global__ void k_init() {
    int i = blockIdx.x * blockDim.x + threadIdx.x;
    if (i < 4 * DHID) ((float*)g_h)[i] = (i < DHID) ? 0.0f : SENT;
}

// ---------------------------------------------------------------------------
// pack: transpose h-part of each gate weight [3072,2048] -> bf16 [g][j][k]
// ---------------------------------------------------------------------------
__global__ void k_pack(Ptrs p) {
    __shared__ float tile[32][33];
    int g  = blockIdx.z;
    int k0 = blockIdx.x * 32;
    int j0 = blockIdx.y * 32;
    tile[threadIdx.y][threadIdx.x] =
        p.W[g][(size_t)(DIN + k0 + threadIdx.y) * DHID + j0 + threadIdx.x];
    __syncthreads();
    g_wh[((size_t)g * DHID + j0 + threadIdx.y) * DHID + k0 + threadIdx.x] =
        __float2bfloat16(tile[threadIdx.x][threadIdx.y]);
}

// ---------------------------------------------------------------------------
// xproj GEMM: g_xproj[t][g*2048+j] = b_g[j] + sum_k x[t,k] * W_g[k,j]
// 128x128 tile, BK=8, 256 threads, 8x8 microtile, fp32.
// ---------------------------------------------------------------------------
__global__ __launch_bounds__(256, 2) void k_xproj(const float* __restrict__ x, Ptrs p) {
    __shared__ float As[8][128];   // [k][m]
    __shared__ float Bs[8][128];   // [k][n]
    int n0 = blockIdx.x * 128;
    int m0 = blockIdx.y * 128;
    int g  = n0 >> 11;
    int jb = n0 & (DHID - 1);
    const float* __restrict__ W = p.W[g];
    int tid  = threadIdx.x;
    int arow = tid >> 1, akq = (tid & 1) << 2;
    int brow = tid >> 5, bcol = (tid & 31) << 2;
    int tm = (tid >> 4) << 3;
    int tn = (tid & 15) << 3;
    float acc[8][8] = {};

    for (int k0 = 0; k0 < DIN; k0 += 8) {
        float4 av = *(const float4*)&x[(size_t)(m0 + arow) * DIN + k0 + akq];
        float4 bv = *(const float4*)&W[(size_t)(k0 + brow) * DHID + jb + bcol];
        __syncthreads();
        As[akq + 0][arow] = av.x;
        As[akq + 1][arow] = av.y;
        As[akq + 2][arow] = av.z;
        As[akq + 3][arow] = av.w;
        *(float4*)&Bs[brow][bcol] = bv;
        __syncthreads();
#pragma unroll
        for (int kk = 0; kk < 8; kk++) {
            float4 a0 = *(const float4*)&As[kk][tm];
            float4 a1 = *(const float4*)&As[kk][tm + 4];
            float4 b0 = *(const float4*)&Bs[kk][tn];
            float4 b1 = *(const float4*)&Bs[kk][tn + 4];
            float am[8] = {a0.x, a0.y, a0.z, a0.w, a1.x, a1.y, a1.z, a1.w};
            float bn[8] = {b0.x, b0.y, b0.z, b0.w, b1.x, b1.y, b1.z, b1.w};
#pragma unroll
            for (int mm = 0; mm < 8; mm++)
#pragma unroll
                for (int nn = 0; nn < 8; nn++)
                    acc[mm][nn] += am[mm] * bn[nn];
        }
    }

    const float* bg = p.b[g];
#pragma unroll
    for (int mm = 0; mm < 8; mm++) {
        int m = m0 + tm + mm;
#pragma unroll
        for (int nn = 0; nn < 8; nn += 4) {
            float4 o;
            o.x = acc[mm][nn + 0] + bg[jb + tn + nn + 0];
            o.y = acc[mm][nn + 1] + bg[jb + tn + nn + 1];
            o.z = acc[mm][nn + 2] + bg[jb + tn + nn + 2];
            o.w = acc[mm][nn + 3] + bg[jb + tn + nn + 3];
            *(float4*)&g_xproj[(size_t)m * NPROJ + n0 + tn + nn] = o;
        }
    }
}

// ---------------------------------------------------------------------------
// recurrent persistent kernel: data-driven sync, free-running warps
// ---------------------------------------------------------------------------
__device__ __forceinline__ float sigm_(float v) { return 1.0f / (1.0f + __expf(-v)); }
__device__ __forceinline__ float tanh_(float v) { return 2.0f / (1.0f + __expf(-2.0f * v)) - 1.0f; }

// bf16 pair (packed u32) -> two f32 via pure ALU ops
#define BF2LO(u) __int_as_float((u) << 16)
#define BF2HI(u) __int_as_float((u) & 0xffff0000u)

__global__ void __launch_bounds__(RTHREADS, 1) k_rec() {
    extern __shared__ __nv_bfloat16 sw[];   // [(jl*4+g)*2048 + k]
    int tid  = threadIdx.x;
    int lane = tid & 31;
    int w    = tid >> 5;                 // warp id, owns j-pair (2w, 2w+1)
    int j0   = blockIdx.x * NJ;
    int nj   = DHID - j0; if (nj > NJ) nj = NJ;

    // ---- stage this CTA's bf16 weight slice into smem (one time) ----
    {
        int nvec = nj * 4 * (DHID / 8);            // uint4 = 8 bf16, 256 per row
        uint4* dst = (uint4*)sw;
        for (int t = tid; t < nvec; t += RTHREADS) {
            int r  = t >> 8;                        // smem row = jl*4+g
            int c  = t & 255;
            int jl = r >> 2, g = r & 3;
            const uint4* src = (const uint4*)(g_wh + ((size_t)g * DHID + j0 + jl) * DHID);
            dst[(r << 8) + c] = src[c];
        }
    }
    __syncthreads();   // only intra-CTA sync in the whole kernel

    int  jg0     = j0 + 2 * w;
    bool myj     = (lane < 2) && (2 * w + lane < nj);  // lanes 0/1 own one j each
    bool warp_on = (2 * w < nj);
    if (!warp_on) return;                               // inactive warps exit
    const __nv_bfloat16* wrow0 = sw + (size_t)(2 * w)     * 4 * DHID;
    const __nv_bfloat16* wrow1 = sw + (size_t)(2 * w + 1) * 4 * DHID;
    float cst = 0.0f;                                   // c state in lanes 0/1

#pragma unroll 1
    for (int s = 0; s < SEQ; ++s) {
        const float* hprev = g_h[s & 3];          // h[s]   (poll target)
        float*       hnext = g_h[(s + 1) & 3];    // h[s+1] (we write)
        float*       hclr  = g_h[(s + 2) & 3];    // holds h[s-2]: reads provably done

        // re-sentinel our own future slots (ordered before h store by st.release)
        if (myj) st_rlx(hclr + jg0 + lane, SENT);

        // x-projection values for this lane's j (overlaps the h poll below)
        float xv0 = 0.f, xv1 = 0.f, xv2 = 0.f, xv3 = 0.f;
        if (myj) {
            const float* xp = g_xproj + (size_t)s * NPROJ + jg0 + lane;
            xv0 = __ldcg(xp);
            xv1 = __ldcg(xp + DHID);
            xv2 = __ldcg(xp + 2 * DHID);
            xv3 = __ldcg(xp + 3 * DHID);
        }

        float a00 = 0.f, a01 = 0.f, a02 = 0.f, a03 = 0.f;  // j = jg0
        float a10 = 0.f, a11 = 0.f, a12 = 0.f, a13 = 0.f;  // j = jg0+1
#pragma unroll
        for (int i = 0; i < 8; i++) {
            int k0 = (i << 8) + (lane << 3);        // 8 k per lane per iter
            float4 h0, h1;
            for (;;) {                              // the load IS the barrier
                h0 = ld_vol4(hprev + k0);
                h1 = ld_vol4(hprev + k0 + 4);
                bool bad = (h0.x == SENT) | (h0.y == SENT) | (h0.z == SENT) |
                           (h0.w == SENT) | (h1.x == SENT) | (h1.y == SENT) |
                           (h1.z == SENT) | (h1.w == SENT);
                if (!bad) break;
            }
#define GATE(acc, base, goff)                                                 \
            {                                                                 \
                uint4 wv = *(const uint4*)((base) + (goff) + k0);             \
                acc += BF2LO(wv.x) * h0.x + BF2HI(wv.x) * h0.y;               \
                acc += BF2LO(wv.y) * h0.z + BF2HI(wv.y) * h0.w;               \
                acc += BF2LO(wv.z) * h1.x + BF2HI(wv.z) * h1.y;               \
                acc += BF2LO(wv.w) * h1.z + BF2HI(wv.w) * h1.w;               \
            }
            GATE(a00, wrow0, 0)
            GATE(a01, wrow0, DHID)
            GATE(a02, wrow0, 2 * DHID)
            GATE(a03, wrow0, 3 * DHID)
            GATE(a10, wrow1, 0)
            GATE(a11, wrow1, DHID)
            GATE(a12, wrow1, 2 * DHID)
            GATE(a13, wrow1, 3 * DHID)
#undef GATE
        }
#pragma unroll
        for (int off = 16; off; off >>= 1) {
            a00 += __shfl_xor_sync(0xffffffffu, a00, off);
            a01 += __shfl_xor_sync(0xffffffffu, a01, off);
            a02 += __shfl_xor_sync(0xffffffffu, a02, off);
            a03 += __shfl_xor_sync(0xffffffffu, a03, off);
            a10 += __shfl_xor_sync(0xffffffffu, a10, off);
            a11 += __shfl_xor_sync(0xffffffffu, a11, off);
            a12 += __shfl_xor_sync(0xffffffffu, a12, off);
            a13 += __shfl_xor_sync(0xffffffffu, a13, off);
        }
        if (myj) {
            float s0 = (lane == 0) ? a00 : a10;
            float s1 = (lane == 0) ? a01 : a11;
            float s2 = (lane == 0) ? a02 : a12;
            float s3 = (lane == 0) ? a03 : a13;
            float f  = sigm_(s0 + xv0);
            float ig = sigm_(s1 + xv1);
            float gg = tanh_(s2 + xv2);
            float oo = sigm_(s3 + xv3);
            cst = cst * f + ig * gg;
            float hn = tanh_(cst) * oo;
            st_rel(hnext + jg0 + lane, hn);   // release: orders clear before publish
        }
    }
}

// ---------------------------------------------------------------------------
// output: out[o] = b_out[o] + sum_j h_last[j] * W_out[j,o]
// h[2048] lands in buffer (2048 & 3) == 0.
// ---------------------------------------------------------------------------
__global__ __launch_bounds__(256) void k_out(const float* __restrict__ Wout,
                                             const float* __restrict__ bout,
                                             float* __restrict__ out) {
    __shared__ float red[4][64];
    int ol  = threadIdx.x & 63;
    int seg = threadIdx.x >> 6;
    int o   = blockIdx.x * 64 + ol;
    const float* h = g_h[0];
    float acc = 0.0f;
    int kbeg = seg * 512;
#pragma unroll 4
    for (int k = kbeg; k < kbeg + 512; ++k)
        acc += h[k] * Wout[(size_t)k * DOUT + o];
    red[seg][ol] = acc;
    __syncthreads();
    if (seg == 0)
        out[o] = bout[o] + red[0][ol] + red[1][ol] + red[2][ol] + red[3][ol];
}

// ---------------------------------------------------------------------------
extern "C" void kernel_launch(void* const* d_in, const int* in_sizes, int n_in,
                              void* d_out, int out_size) {
    const float* x = (const float*)d_in[0];
    Ptrs p;
    p.W[0] = (const float*)d_in[1]; p.b[0] = (const float*)d_in[2];   // f
    p.W[1] = (const float*)d_in[3]; p.b[1] = (const float*)d_in[4];   // i
    p.W[2] = (const float*)d_in[5]; p.b[2] = (const float*)d_in[6];   // c (g)
    p.W[3] = (const float*)d_in[7]; p.b[3] = (const float*)d_in[8];   // o
    const float* Wout = (const float*)d_in[9];
    const float* bout = (const float*)d_in[10];

    cudaFuncSetAttribute(k_rec, cudaFuncAttributeMaxDynamicSharedMemorySize, SMEM_REC);

    k_init<<<8, 1024>>>();
    k_pack<<<dim3(DHID / 32, DHID / 32, 4), dim3(32, 32)>>>(p);
    k_xproj<<<dim3(NPROJ / 128, SEQ / 128), 256>>>(x, p);
    k_rec<<<RGRID, RTHREADS, SMEM_REC>>>();
    k_out<<<DOUT / 64, 256>>>(Wout, bout, (float*)d_out);
}

// round 6
// speedup vs baseline: 3.4918x; 3.4918x over previous
#include <cuda_runtime.h>
#include <cuda_fp16.h>
#include <cuda_bf16.h>

#define SEQ   2048
#define DIN   1024
#define DHID  2048
#define DOUT  512
#define NPROJ 8192   // 4 gates * DHID

// ---- recurrent kernel geometry ----
#define NJ       14             // hidden units per CTA (2 per warp)
#define RWARPS   7
#define RTHREADS (RWARPS * 32)  // 224
#define RGRID    147            // ceil(2048/14), <= 148 SMs -> all co-resident
#define SMEM_REC (NJ * 4 * DHID * 2)  // 229376 B of bf16 weights

// ---- device scratch (allocation-free requirement) ----
__device__ float          g_xproj[(size_t)SEQ * NPROJ];   // 64 MB: [t][g*2048+j]
__device__ __nv_bfloat16  g_wh[(size_t)4 * DHID * DHID];  // 32 MB: [(g*2048+j)*2048+k]
__device__ float          g_h[2][DHID];                   // double-buffered hidden state
__device__ unsigned       g_cnt;                          // monotonic barrier counter

struct Ptrs { const float* W[4]; const float* b[4]; };

// ---- barrier primitives: release-RED arrival + acquire-load spin ----
__device__ __forceinline__ void red_release_add(unsigned* p) {
    asm volatile("red.release.gpu.global.add.u32 [%0], 1;" :: "l"(p) : "memory");
}
__device__ __forceinline__ unsigned ld_acq(const unsigned* p) {
    unsigned v;
    asm volatile("ld.acquire.gpu.global.u32 %0, [%1];" : "=r"(v) : "l"(p) : "memory");
    return v;
}

// ---------------------------------------------------------------------------
// init: zero h buffer 0, reset counter (runs every launch -> graph-replay safe)
// ---------------------------------------------------------------------------
__global__ void k_init() {
    int i = blockIdx.x * blockDim.x + threadIdx.x;
    if (i < 2 * DHID) ((float*)g_h)[i] = 0.0f;
    if (i == 0) g_cnt = 0u;
}

// ---------------------------------------------------------------------------
// pack: transpose h-part of each gate weight [3072,2048] -> bf16 [g][j][k]
// ---------------------------------------------------------------------------
__global__ void k_pack(Ptrs p) {
    __shared__ float tile[32][33];
    int g  = blockIdx.z;
    int k0 = blockIdx.x * 32;
    int j0 = blockIdx.y * 32;
    tile[threadIdx.y][threadIdx.x] =
        p.W[g][(size_t)(DIN + k0 + threadIdx.y) * DHID + j0 + threadIdx.x];
    __syncthreads();
    g_wh[((size_t)g * DHID + j0 + threadIdx.y) * DHID + k0 + threadIdx.x] =
        __float2bfloat16(tile[threadIdx.x][threadIdx.y]);
}

// ---------------------------------------------------------------------------
// xproj GEMM: g_xproj[t][g*2048+j] = b_g[j] + sum_k x[t,k] * W_g[k,j]
// 128x128 tile, BK=8, 256 threads, 8x8 microtile, fp32. (unchanged, known-good)
// ---------------------------------------------------------------------------
__global__ __launch_bounds__(256, 2) void k_xproj(const float* __restrict__ x, Ptrs p) {
    __shared__ float As[8][128];   // [k][m]
    __shared__ float Bs[8][128];   // [k][n]
    int n0 = blockIdx.x * 128;
    int m0 = blockIdx.y * 128;
    int g  = n0 >> 11;
    int jb = n0 & (DHID - 1);
    const float* __restrict__ W = p.W[g];
    int tid  = threadIdx.x;
    int arow = tid >> 1, akq = (tid & 1) << 2;
    int brow = tid >> 5, bcol = (tid & 31) << 2;
    int tm = (tid >> 4) << 3;
    int tn = (tid & 15) << 3;
    float acc[8][8] = {};

    for (int k0 = 0; k0 < DIN; k0 += 8) {
        float4 av = *(const float4*)&x[(size_t)(m0 + arow) * DIN + k0 + akq];
        float4 bv = *(const float4*)&W[(size_t)(k0 + brow) * DHID + jb + bcol];
        __syncthreads();
        As[akq + 0][arow] = av.x;
        As[akq + 1][arow] = av.y;
        As[akq + 2][arow] = av.z;
        As[akq + 3][arow] = av.w;
        *(float4*)&Bs[brow][bcol] = bv;
        __syncthreads();
#pragma unroll
        for (int kk = 0; kk < 8; kk++) {
            float4 a0 = *(const float4*)&As[kk][tm];
            float4 a1 = *(const float4*)&As[kk][tm + 4];
            float4 b0 = *(const float4*)&Bs[kk][tn];
            float4 b1 = *(const float4*)&Bs[kk][tn + 4];
            float am[8] = {a0.x, a0.y, a0.z, a0.w, a1.x, a1.y, a1.z, a1.w};
            float bn[8] = {b0.x, b0.y, b0.z, b0.w, b1.x, b1.y, b1.z, b1.w};
#pragma unroll
            for (int mm = 0; mm < 8; mm++)
#pragma unroll
                for (int nn = 0; nn < 8; nn++)
                    acc[mm][nn] += am[mm] * bn[nn];
        }
    }

    const float* bg = p.b[g];
#pragma unroll
    for (int mm = 0; mm < 8; mm++) {
        int m = m0 + tm + mm;
#pragma unroll
        for (int nn = 0; nn < 8; nn += 4) {
            float4 o;
            o.x = acc[mm][nn + 0] + bg[jb + tn + nn + 0];
            o.y = acc[mm][nn + 1] + bg[jb + tn + nn + 1];
            o.z = acc[mm][nn + 2] + bg[jb + tn + nn + 2];
            o.w = acc[mm][nn + 3] + bg[jb + tn + nn + 3];
            *(float4*)&g_xproj[(size_t)m * NPROJ + n0 + tn + nn] = o;
        }
    }
}

// ---------------------------------------------------------------------------
// recurrent persistent kernel
// ---------------------------------------------------------------------------
__device__ __forceinline__ float sigm_(float v) { return 1.0f / (1.0f + __expf(-v)); }
__device__ __forceinline__ float tanh_(float v) { return 2.0f / (1.0f + __expf(-2.0f * v)) - 1.0f; }

// pack two adjacent floats into an f32x2 (register pair; mov.b64 usually folds)
__device__ __forceinline__ unsigned long long pack2(float lo, float hi) {
    unsigned long long p;
    asm("mov.b64 %0, {%1, %2};" : "=l"(p) : "f"(lo), "f"(hi));
    return p;
}
// unpack f32x2 pair and horizontal-add
__device__ __forceinline__ float pair_sum(unsigned long long p) {
    float lo, hi;
    asm("mov.b64 {%0, %1}, %2;" : "=f"(lo), "=f"(hi) : "l"(p));
    return lo + hi;
}

__global__ void __launch_bounds__(RTHREADS, 1) k_rec() {
    extern __shared__ __nv_bfloat16 sw[];   // [(jl*4+g)*2048 + k]
    int tid  = threadIdx.x;
    int lane = tid & 31;
    int w    = tid >> 5;                 // warp id, owns j-pair (2w, 2w+1)
    int j0   = blockIdx.x * NJ;
    int nj   = DHID - j0; if (nj > NJ) nj = NJ;

    // ---- stage this CTA's bf16 weight slice into smem (one time) ----
    {
        int nvec = nj * 4 * (DHID / 8);            // uint4 = 8 bf16, 256 per row
        uint4* dst = (uint4*)sw;
        for (int t = tid; t < nvec; t += RTHREADS) {
            int r  = t >> 8;                        // smem row = jl*4+g
            int c  = t & 255;
            int jl = r >> 2, g = r & 3;
            const uint4* src = (const uint4*)(g_wh + ((size_t)g * DHID + j0 + jl) * DHID);
            dst[(r << 8) + c] = src[c];
        }
    }
    __syncthreads();

    int  jg0     = j0 + 2 * w;
    bool myj     = (lane < 2) && (2 * w + lane < nj);  // lanes 0/1 own one j each
    bool warp_on = (2 * w < nj);
    const __nv_bfloat16* wrow0 = sw + (size_t)(2 * w)     * 4 * DHID;
    const __nv_bfloat16* wrow1 = sw + (size_t)(2 * w + 1) * 4 * DHID;
    float cst = 0.0f;                                   // c state in lanes 0/1

    // prefetch xproj for step 0 (h-independent)
    float xv0 = 0.f, xv1 = 0.f, xv2 = 0.f, xv3 = 0.f;
    if (myj) {
        const float* xp = g_xproj + jg0 + lane;
        xv0 = __ldcg(xp);
        xv1 = __ldcg(xp + DHID);
        xv2 = __ldcg(xp + 2 * DHID);
        xv3 = __ldcg(xp + 3 * DHID);
    }

#pragma unroll 1
    for (int s = 0; s < SEQ; ++s) {
        const float* hprev = g_h[s & 1];
        float*       hnext = g_h[(s + 1) & 1];

        if (warp_on) {
            // f32x2 accumulator pairs, one per (j, gate)
            unsigned long long a00 = 0, a01 = 0, a02 = 0, a03 = 0;  // j = jg0
            unsigned long long a10 = 0, a11 = 0, a12 = 0, a13 = 0;  // j = jg0+1
#pragma unroll
            for (int i = 0; i < 8; i++) {
                int k0 = (i << 8) + (lane << 3);    // 8 k per lane per iter
                float4 h0 = __ldcg((const float4*)(hprev + k0));
                float4 h1 = __ldcg((const float4*)(hprev + k0 + 4));
                unsigned long long hp0 = pack2(h0.x, h0.y);
                unsigned long long hp1 = pack2(h0.z, h0.w);
                unsigned long long hp2 = pack2(h1.x, h1.y);
                unsigned long long hp3 = pack2(h1.z, h1.w);
                // per gate: 4 bf16-pairs -> 4 packed FFMA2 (8 MACs)
#define GATE(acc, base, goff)                                                  \
                {                                                              \
                    uint4 wv = *(const uint4*)((base) + (goff) + k0);          \
                    asm("{\n\t"                                                \
                        ".reg .b32 lo, hi;\n\t"                                \
                        ".reg .b64 p;\n\t"                                     \
                        "shl.b32 lo, %1, 16; and.b32 hi, %1, 0xffff0000;\n\t"  \
                        "mov.b64 p, {lo, hi}; fma.rn.f32x2 %0, p, %5, %0;\n\t" \
                        "shl.b32 lo, %2, 16; and.b32 hi, %2, 0xffff0000;\n\t"  \
                        "mov.b64 p, {lo, hi}; fma.rn.f32x2 %0, p, %6, %0;\n\t" \
                        "shl.b32 lo, %3, 16; and.b32 hi, %3, 0xffff0000;\n\t"  \
                        "mov.b64 p, {lo, hi}; fma.rn.f32x2 %0, p, %7, %0;\n\t" \
                        "shl.b32 lo, %4, 16; and.b32 hi, %4, 0xffff0000;\n\t"  \
                        "mov.b64 p, {lo, hi}; fma.rn.f32x2 %0, p, %8, %0;\n\t" \
                        "}"                                                    \
                        : "+l"(acc)                                            \
                        : "r"(wv.x), "r"(wv.y), "r"(wv.z), "r"(wv.w),          \
                          "l"(hp0), "l"(hp1), "l"(hp2), "l"(hp3));             \
                }
                GATE(a00, wrow0, 0)
                GATE(a01, wrow0, DHID)
                GATE(a02, wrow0, 2 * DHID)
                GATE(a03, wrow0, 3 * DHID)
                GATE(a10, wrow1, 0)
                GATE(a11, wrow1, DHID)
                GATE(a12, wrow1, 2 * DHID)
                GATE(a13, wrow1, 3 * DHID)
#undef GATE
            }
            // pair horizontal add, then warp tree-reduce
            float r00 = pair_sum(a00), r01 = pair_sum(a01);
            float r02 = pair_sum(a02), r03 = pair_sum(a03);
            float r10 = pair_sum(a10), r11 = pair_sum(a11);
            float r12 = pair_sum(a12), r13 = pair_sum(a13);
#pragma unroll
            for (int off = 16; off; off >>= 1) {
                r00 += __shfl_xor_sync(0xffffffffu, r00, off);
                r01 += __shfl_xor_sync(0xffffffffu, r01, off);
                r02 += __shfl_xor_sync(0xffffffffu, r02, off);
                r03 += __shfl_xor_sync(0xffffffffu, r03, off);
                r10 += __shfl_xor_sync(0xffffffffu, r10, off);
                r11 += __shfl_xor_sync(0xffffffffu, r11, off);
                r12 += __shfl_xor_sync(0xffffffffu, r12, off);
                r13 += __shfl_xor_sync(0xffffffffu, r13, off);
            }
            if (myj) {
                float s0 = (lane == 0) ? r00 : r10;
                float s1 = (lane == 0) ? r01 : r11;
                float s2 = (lane == 0) ? r02 : r12;
                float s3 = (lane == 0) ? r03 : r13;
                float f  = sigm_(s0 + xv0);
                float ig = sigm_(s1 + xv1);
                float gg = tanh_(s2 + xv2);
                float oo = sigm_(s3 + xv3);
                cst = cst * f + ig * gg;
                float hn = tanh_(cst) * oo;
                __stcg(hnext + jg0 + lane, hn);   // weak store; ordered by red.release
            }
        }

        if (s < SEQ - 1) {
            // prefetch next step's xproj BEFORE the barrier (hides its latency)
            if (myj) {
                const float* xp = g_xproj + (size_t)(s + 1) * NPROJ + jg0 + lane;
                xv0 = __ldcg(xp);
                xv1 = __ldcg(xp + DHID);
                xv2 = __ldcg(xp + 2 * DHID);
                xv3 = __ldcg(xp + 3 * DHID);
            }
            __syncthreads();                       // CTA's h stores all issued
            if (tid == 0) {
                red_release_add(&g_cnt);           // arrive: orders prior .cg stores
                unsigned tgt = (unsigned)(s + 1) * (unsigned)RGRID;
                while (ld_acq(&g_cnt) < tgt) { }   // single-word spin, 1 thread/CTA
            }
            __syncthreads();                       // release whole CTA into s+1
        }
    }
}

// ---------------------------------------------------------------------------
// output: out[o] = b_out[o] + sum_j h_last[j] * W_out[j,o]   (h_last = g_h[0])
// ---------------------------------------------------------------------------
__global__ __launch_bounds__(256) void k_out(const float* __restrict__ Wout,
                                             const float* __restrict__ bout,
                                             float* __restrict__ out) {
    __shared__ float red[4][64];
    int ol  = threadIdx.x & 63;
    int seg = threadIdx.x >> 6;
    int o   = blockIdx.x * 64 + ol;
    const float* h = g_h[0];      // SEQ even -> final h lands in buffer 0
    float acc = 0.0f;
    int kbeg = seg * 512;
#pragma unroll 4
    for (int k = kbeg; k < kbeg + 512; ++k)
        acc += h[k] * Wout[(size_t)k * DOUT + o];
    red[seg][ol] = acc;
    __syncthreads();
    if (seg == 0)
        out[o] = bout[o] + red[0][ol] + red[1][ol] + red[2][ol] + red[3][ol];
}

// ---------------------------------------------------------------------------
extern "C" void kernel_launch(void* const* d_in, const int* in_sizes, int n_in,
                              void* d_out, int out_size) {
    const float* x = (const float*)d_in[0];
    Ptrs p;
    p.W[0] = (const float*)d_in[1]; p.b[0] = (const float*)d_in[2];   // f
    p.W[1] = (const float*)d_in[3]; p.b[1] = (const float*)d_in[4];   // i
    p.W[2] = (const float*)d_in[5]; p.b[2] = (const float*)d_in[6];   // c (g)
    p.W[3] = (const float*)d_in[7]; p.b[3] = (const float*)d_in[8];   // o
    const float* Wout = (const float*)d_in[9];
    const float* bout = (const float*)d_in[10];

    cudaFuncSetAttribute(k_rec, cudaFuncAttributeMaxDynamicSharedMemorySize, SMEM_REC);

    k_init<<<4, 1024>>>();
    k_pack<<<dim3(DHID / 32, DHID / 32, 4), dim3(32, 32)>>>(p);
    k_xproj<<<dim3(NPROJ / 128, SEQ / 128), 256>>>(x, p);
    k_rec<<<RGRID, RTHREADS, SMEM_REC>>>();
    k_out<<<DOUT / 64, 256>>>(Wout, bout, (float*)d_out);
}